// round 1
// baseline (speedup 1.0000x reference)
#include <cuda_runtime.h>

// SpikeLayer LIF scan: x [B=64, T=8, C=256, H=32, W=32] f32 -> spikes same shape.
// mem = mem*0.25 + x; spike = (mem - 0.5) > 0; mem = (1-spike)*mem.
// One thread owns 4 contiguous neurons (float4 along W) for all 8 timesteps;
// recurrence state stays in registers. Pure streaming kernel: 1 GiB traffic.

#define LIF_T 8
#define VTH 0.5f
#define DECAY 0.25f

__global__ __launch_bounds__(256) void lif_scan_kernel(
    const float4* __restrict__ x, float4* __restrict__ out, long chw4)
{
    // chw4 = C*H*W/4 float4 vectors per (b,t) slice
    long i = (long)blockIdx.x * blockDim.x + threadIdx.x; // [0, B*chw4)
    long b = i / chw4;
    long n = i - b * chw4;
    long base = b * (LIF_T * chw4) + n;

    float4 v[LIF_T];
    // Front-batched independent loads: MLP = 8 LDG.128
    #pragma unroll
    for (int t = 0; t < LIF_T; t++)
        v[t] = x[base + (long)t * chw4];

    float mx = 0.f, my = 0.f, mz = 0.f, mw = 0.f;
    #pragma unroll
    for (int t = 0; t < LIF_T; t++) {
        float sx, sy, sz, sw;
        mx = fmaf(mx, DECAY, v[t].x);
        my = fmaf(my, DECAY, v[t].y);
        mz = fmaf(mz, DECAY, v[t].z);
        mw = fmaf(mw, DECAY, v[t].w);
        sx = (mx > VTH) ? 1.f : 0.f;
        sy = (my > VTH) ? 1.f : 0.f;
        sz = (mz > VTH) ? 1.f : 0.f;
        sw = (mw > VTH) ? 1.f : 0.f;
        // hard reset where spiked
        mx = (sx != 0.f) ? 0.f : mx;
        my = (sy != 0.f) ? 0.f : my;
        mz = (sz != 0.f) ? 0.f : mz;
        mw = (sw != 0.f) ? 0.f : mw;
        // reuse v[t] registers for the spike output
        v[t].x = sx; v[t].y = sy; v[t].z = sz; v[t].w = sw;
    }

    #pragma unroll
    for (int t = 0; t < LIF_T; t++)
        out[base + (long)t * chw4] = v[t];
}

extern "C" void kernel_launch(void* const* d_in, const int* in_sizes, int n_in,
                              void* d_out, int out_size)
{
    const float4* x = (const float4*)d_in[0];
    float4* out = (float4*)d_out;

    // in_sizes[0] = B*T*C*H*W = 134217728 for the bench shape.
    long total = (long)in_sizes[0];
    long total4 = total / 4;                 // float4 vectors in whole tensor
    long neurons4 = total4 / LIF_T;          // float4 vectors per timestep across batch
    long chw4 = 256L * 32L * 32L / 4L;       // 65536 per (b,t) slice

    int threads = 256;
    long blocks = (neurons4 + threads - 1) / threads;

    lif_scan_kernel<<<(unsigned)blocks, threads>>>(x, out, chw4);
}

// round 2
// speedup vs baseline: 1.0030x; 1.0030x over previous
#include <cuda_runtime.h>

// SpikeLayer LIF scan: x [B=64, T=8, C=256, H=32, W=32] f32 -> spikes same shape.
// mem = mem*0.25 + x; spike = (mem - 0.5) > 0; mem = (1-spike)*mem.
// One thread owns 4 contiguous neurons (float4) for all 8 timesteps; recurrence
// in registers. Streaming kernel (1 GiB): use evict-first loads (__ldcs) and
// streaming stores (__stcs) since neither stream is ever reused, and a 2D grid
// (y = batch) to kill the 64-bit division in the index prologue.

#define LIF_T 8
#define VTH 0.5f
#define DECAY 0.25f
#define CHW4 (256L * 32L * 32L / 4L)   // float4 vectors per (b,t) slice = 65536

__global__ __launch_bounds__(256) void lif_scan_kernel(
    const float4* __restrict__ x, float4* __restrict__ out)
{
    long n    = (long)blockIdx.x * blockDim.x + threadIdx.x;  // [0, CHW4)
    long base = (long)blockIdx.y * (LIF_T * CHW4) + n;

    float4 v[LIF_T];
    // Front-batched independent loads (MLP=8), evict-first: stream, no reuse.
    #pragma unroll
    for (int t = 0; t < LIF_T; t++)
        v[t] = __ldcs(&x[base + (long)t * CHW4]);

    float mx = 0.f, my = 0.f, mz = 0.f, mw = 0.f;
    #pragma unroll
    for (int t = 0; t < LIF_T; t++) {
        mx = fmaf(mx, DECAY, v[t].x);
        my = fmaf(my, DECAY, v[t].y);
        mz = fmaf(mz, DECAY, v[t].z);
        mw = fmaf(mw, DECAY, v[t].w);
        float sx = (mx > VTH) ? 1.f : 0.f;
        float sy = (my > VTH) ? 1.f : 0.f;
        float sz = (mz > VTH) ? 1.f : 0.f;
        float sw = (mw > VTH) ? 1.f : 0.f;
        // hard reset where spiked
        mx = (sx != 0.f) ? 0.f : mx;
        my = (sy != 0.f) ? 0.f : my;
        mz = (sz != 0.f) ? 0.f : mz;
        mw = (sw != 0.f) ? 0.f : mw;
        v[t].x = sx; v[t].y = sy; v[t].z = sz; v[t].w = sw;
    }

    #pragma unroll
    for (int t = 0; t < LIF_T; t++)
        __stcs(&out[base + (long)t * CHW4], v[t]);
}

extern "C" void kernel_launch(void* const* d_in, const int* in_sizes, int n_in,
                              void* d_out, int out_size)
{
    const float4* x = (const float4*)d_in[0];
    float4* out = (float4*)d_out;

    long total   = (long)in_sizes[0];          // B*T*C*H*W
    long batches = total / (LIF_T * CHW4 * 4); // = 64 for bench shape

    dim3 grid((unsigned)(CHW4 / 256), (unsigned)batches, 1);
    lif_scan_kernel<<<grid, 256>>>(x, out);
}